// round 1
// baseline (speedup 1.0000x reference)
#include <cuda_runtime.h>
#include <math.h>
#include <float.h>

// Problem constants
#define Bc    8
#define Fc    16
#define NSc   196
#define Jc    24
#define Hc    8
#define DHc   64
#define DIMc  512
#define ROTc  32
#define Nc    3160          // J + F*NS
#define MROWS (Bc*Nc)       // 25280
#define BHc   64            // B*H
#define NSP   3136          // F*NS
#define SKR   220           // J + NS (spatial key rows)

// -------- scratch (device globals; no runtime allocation) --------
__device__ float g_qkv[(size_t)MROWS * 1536];     // ~155 MB
__device__ float g_Q   [(size_t)BHc * Nc  * 64];  // scaled (+roped spatial rows)
__device__ float g_Kraw[(size_t)BHc * Nc  * 64];  // un-roped K (joints attn keys)
__device__ float g_Krope[(size_t)BHc * NSP * 64]; // roped spatial K
__device__ float g_V   [(size_t)BHc * Nc  * 64];
__device__ float g_AO  [(size_t)MROWS * 512];     // attention out, (b,n,h*d) layout

// -------- block reduction helpers --------
template<int NW>
__device__ __forceinline__ float block_max(float v, float* red, int tid) {
    #pragma unroll
    for (int o = 16; o; o >>= 1) v = fmaxf(v, __shfl_xor_sync(0xffffffffu, v, o));
    if ((tid & 31) == 0) red[tid >> 5] = v;
    __syncthreads();
    float r = red[0];
    #pragma unroll
    for (int w = 1; w < NW; w++) r = fmaxf(r, red[w]);
    __syncthreads();
    return r;
}

template<int NW>
__device__ __forceinline__ float block_sum(float v, float* red, int tid) {
    #pragma unroll
    for (int o = 16; o; o >>= 1) v += __shfl_xor_sync(0xffffffffu, v, o);
    if ((tid & 31) == 0) red[tid >> 5] = v;
    __syncthreads();
    float r = red[0];
    #pragma unroll
    for (int w = 1; w < NW; w++) r += red[w];
    __syncthreads();
    return r;
}

// -------- SGEMM: C[M,N] = A[M,K] @ B[K,N] (+bias), tiles 64x128x16 --------
// M % 64 == 0, N % 128 == 0, K % 16 == 0 (all hold for our shapes)
__global__ void sgemm64x128(const float* __restrict__ A, const float* __restrict__ Bm,
                            const float* __restrict__ bias, float* __restrict__ C,
                            int M, int N, int K) {
    __shared__ float As[16][68];   // [k][m], padded to keep float4 rows aligned
    __shared__ float Bs[16][128];
    int tid = threadIdx.x;         // 256
    int tx = tid & 15;             // col group (8 cols each)
    int ty = tid >> 4;             // row group (4 rows each)
    int row0 = blockIdx.y * 64;
    int col0 = blockIdx.x * 128;

    float acc[4][8];
    #pragma unroll
    for (int i = 0; i < 4; i++)
        #pragma unroll
        for (int j = 0; j < 8; j++) acc[i][j] = 0.f;

    for (int k0 = 0; k0 < K; k0 += 16) {
        { // A tile: 64x16 as 256 float4
            int m  = tid >> 2;
            int kq = (tid & 3) * 4;
            float4 av = *reinterpret_cast<const float4*>(A + (size_t)(row0 + m) * K + k0 + kq);
            As[kq + 0][m] = av.x; As[kq + 1][m] = av.y;
            As[kq + 2][m] = av.z; As[kq + 3][m] = av.w;
        }
        #pragma unroll
        for (int t = 0; t < 2; t++) { // B tile: 16x128 as 512 float4
            int i  = tid + t * 256;
            int kk = i >> 5;
            int nq = (i & 31) * 4;
            *reinterpret_cast<float4*>(&Bs[kk][nq]) =
                *reinterpret_cast<const float4*>(Bm + (size_t)(k0 + kk) * N + col0 + nq);
        }
        __syncthreads();
        #pragma unroll
        for (int kk = 0; kk < 16; kk++) {
            float4 a  = *reinterpret_cast<const float4*>(&As[kk][ty * 4]);
            float4 b0 = *reinterpret_cast<const float4*>(&Bs[kk][tx * 8]);
            float4 b1 = *reinterpret_cast<const float4*>(&Bs[kk][tx * 8 + 4]);
            float av[4] = {a.x, a.y, a.z, a.w};
            float bv[8] = {b0.x, b0.y, b0.z, b0.w, b1.x, b1.y, b1.z, b1.w};
            #pragma unroll
            for (int i = 0; i < 4; i++)
                #pragma unroll
                for (int j = 0; j < 8; j++)
                    acc[i][j] += av[i] * bv[j];
        }
        __syncthreads();
    }

    #pragma unroll
    for (int i = 0; i < 4; i++) {
        int r = row0 + ty * 4 + i;
        #pragma unroll
        for (int j = 0; j < 8; j += 4) {
            int c = col0 + tx * 8 + j;
            float4 o;
            o.x = acc[i][j + 0]; o.y = acc[i][j + 1];
            o.z = acc[i][j + 2]; o.w = acc[i][j + 3];
            if (bias) { o.x += bias[c]; o.y += bias[c + 1]; o.z += bias[c + 2]; o.w += bias[c + 3]; }
            *reinterpret_cast<float4*>(C + (size_t)r * N + c) = o;
        }
    }
}

// -------- split qkv into head-major Q/Kraw/Krope/V, apply scale + RoPE --------
__global__ void split_rope_kernel(const float* __restrict__ sinp, const float* __restrict__ cosp) {
    int idx = blockIdx.x * blockDim.x + threadIdx.x;
    const int total = BHc * Nc * 64;
    if (idx >= total) return;
    int d  = idx & 63;
    int n  = (idx >> 6) % Nc;
    int bh = idx / (Nc * 64);
    int b = bh >> 3, h = bh & 7;

    size_t base = ((size_t)b * Nc + n) * 1536 + h * 64;
    float qv = g_qkv[base + d] * 0.125f;       // scale = DH^-0.5 = 1/8
    float kv = g_qkv[base + 512 + d];
    float vv = g_qkv[base + 1024 + d];

    size_t o = ((size_t)bh * Nc + n) * 64 + d;
    g_Kraw[o] = kv;
    g_V[o]    = vv;

    float qo = qv, ko = kv;
    if (n >= Jc) {
        int m = n - Jc;
        int s = m % NSc;
        if (d < ROTc) {
            float c  = cosp[s * ROTc + d];
            float si = sinp[s * ROTc + d];
            if ((d & 1) == 0) {  // out[2i] = t[2i]*cos - t[2i+1]*sin
                float qp = g_qkv[base + d + 1] * 0.125f;
                float kp = g_qkv[base + 512 + d + 1];
                qo = qv * c - qp * si;
                ko = kv * c - kp * si;
            } else {             // out[2i+1] = t[2i+1]*cos + t[2i]*sin
                float qp = g_qkv[base + d - 1] * 0.125f;
                float kp = g_qkv[base + 512 + d - 1];
                qo = qv * c + qp * si;
                ko = kv * c + kp * si;
            }
        }
        g_Krope[((size_t)bh * NSP + m) * 64 + d] = ko;
    }
    g_Q[o] = qo;
}

// -------- joints attention: per (bh, q), softmax over all 3160 un-roped keys --------
__global__ void joints_attn_kernel() {
    int q  = blockIdx.x;   // 0..23
    int bh = blockIdx.y;   // 0..63
    int b = bh >> 3, h = bh & 7;
    __shared__ float sc[Nc];
    __shared__ float qv[64];
    __shared__ float red[8];
    int tid = threadIdx.x; // 128

    const float* Kb = g_Kraw + (size_t)bh * Nc * 64;
    const float* Vb = g_V    + (size_t)bh * Nc * 64;
    if (tid < 64) qv[tid] = g_Q[((size_t)bh * Nc + q) * 64 + tid];
    __syncthreads();

    int lane = tid & 31, warp = tid >> 5;
    for (int j = warp; j < Nc; j += 4) {           // warp per key, coalesced
        const float* kr = Kb + (size_t)j * 64;
        float s = qv[lane] * kr[lane] + qv[lane + 32] * kr[lane + 32];
        #pragma unroll
        for (int o = 16; o; o >>= 1) s += __shfl_xor_sync(0xffffffffu, s, o);
        if (lane == 0) sc[j] = s;
    }
    __syncthreads();

    float mx = -FLT_MAX;
    for (int j = tid; j < Nc; j += 128) mx = fmaxf(mx, sc[j]);
    mx = block_max<4>(mx, red, tid);

    float sum = 0.f;
    for (int j = tid; j < Nc; j += 128) { float e = __expf(sc[j] - mx); sc[j] = e; sum += e; }
    sum = block_sum<4>(sum, red, tid);
    float inv = 1.f / sum;
    __syncthreads();

    // output: 128 threads = 64 dims x 2 key-stripes
    int d = tid & 63, half = tid >> 6;
    float acc = 0.f;
    for (int j = half; j < Nc; j += 2) acc += sc[j] * Vb[(size_t)j * 64 + d];
    __syncthreads();
    if (tid >= 64) qv[d] = acc;
    __syncthreads();
    if (tid < 64) {
        float r = (acc + qv[tid]) * inv;
        g_AO[((size_t)b * Nc + q) * 512 + h * 64 + tid] = r;
    }
}

// -------- spatial attention: per (bh,f): 196 queries over 220 keys (24 joints + 196 roped) --------
__global__ void spatial_attn_kernel() {
    int blk = blockIdx.x;          // 0..1023
    int bh = blk >> 4, f = blk & 15;
    int b = bh >> 3, h = bh & 7;
    extern __shared__ float sm[];
    float* Ks  = sm;               // 220*65
    float* Vs  = Ks  + SKR * 65;   // 220*65
    float* sc0 = Vs  + SKR * 65;   // 224
    float* sc1 = sc0 + 224;        // 224
    float* qv0 = sc1 + 224;        // 64
    float* qv1 = qv0 + 64;         // 64
    float* ob  = qv1 + 64;         // 128
    float* red = ob  + 128;        // 8
    int tid = threadIdx.x;         // 256

    const float* Krb = g_Kraw  + (size_t)bh * Nc  * 64;
    const float* Kpb = g_Krope + (size_t)bh * NSP * 64;
    const float* Vb  = g_V     + (size_t)bh * Nc  * 64;

    for (int i = tid; i < SKR * 64; i += 256) {
        int r = i >> 6, d = i & 63;
        float kv, vv;
        if (r < Jc) { kv = Krb[(size_t)r * 64 + d]; vv = Vb[(size_t)r * 64 + d]; }
        else {
            int m = f * NSc + (r - Jc);
            kv = Kpb[(size_t)m * 64 + d];
            vv = Vb[(size_t)(Jc + m) * 64 + d];
        }
        Ks[r * 65 + d] = kv;
        Vs[r * 65 + d] = vv;
    }
    __syncthreads();

    size_t qrow0 = (size_t)bh * Nc + Jc + f * NSc;
    for (int q0 = 0; q0 < NSc; q0 += 2) {
        if (tid < 64)       qv0[tid]      = g_Q[(qrow0 + q0)     * 64 + tid];
        else if (tid < 128) qv1[tid - 64] = g_Q[(qrow0 + q0 + 1) * 64 + (tid - 64)];
        __syncthreads();

        float s0 = -1e30f, s1 = -1e30f;
        if (tid < SKR) {
            const float* kr = Ks + tid * 65;
            float a0 = 0.f, a1 = 0.f;
            #pragma unroll
            for (int d = 0; d < 64; d++) { float kk = kr[d]; a0 += qv0[d] * kk; a1 += qv1[d] * kk; }
            s0 = a0; s1 = a1;
        }
        float m0 = block_max<8>(s0, red, tid);
        float m1 = block_max<8>(s1, red, tid);
        float e0 = (tid < SKR) ? __expf(s0 - m0) : 0.f;
        float e1 = (tid < SKR) ? __expf(s1 - m1) : 0.f;
        float t0 = block_sum<8>(e0, red, tid);
        float t1 = block_sum<8>(e1, red, tid);
        if (tid < SKR) { sc0[tid] = e0 / t0; sc1[tid] = e1 / t1; }
        __syncthreads();

        // output: 256 threads = 2 queries x 64 dims x 2 key-stripes
        int d = tid & 63, which = (tid >> 6) & 1, half = tid >> 7;
        const float* scp = which ? sc1 : sc0;
        float acc = 0.f;
        for (int j = half; j < SKR; j += 2) acc += scp[j] * Vs[j * 65 + d];
        if (half == 0) ob[tid] = acc;
        __syncthreads();
        if (half == 1) {
            float r = ob[tid - 128] + acc;
            int n = Jc + f * NSc + q0 + which;
            g_AO[((size_t)b * Nc + n) * 512 + h * 64 + d] = r;
        }
        __syncthreads();
    }
}

// -------- launch --------
extern "C" void kernel_launch(void* const* d_in, const int* in_sizes, int n_in,
                              void* d_out, int out_size) {
    const float* x     = (const float*)d_in[0];
    const float* w_qkv = (const float*)d_in[1];
    const float* w_out = (const float*)d_in[2];
    const float* b_out = (const float*)d_in[3];
    const float* sinp  = (const float*)d_in[4];
    const float* cosp  = (const float*)d_in[5];
    float* out = (float*)d_out;

    void *pqkv = nullptr, *pAO = nullptr;
    cudaGetSymbolAddress(&pqkv, g_qkv);
    cudaGetSymbolAddress(&pAO,  g_AO);

    // 1) QKV GEMM: (25280 x 512) @ (512 x 1536)
    dim3 g1(1536 / 128, MROWS / 64);
    sgemm64x128<<<g1, 256>>>(x, w_qkv, nullptr, (float*)pqkv, MROWS, 1536, 512);

    // 2) split + scale + RoPE
    int total = BHc * Nc * 64;
    split_rope_kernel<<<(total + 255) / 256, 256>>>(sinp, cosp);

    // 3) joints attention
    joints_attn_kernel<<<dim3(Jc, BHc), 128>>>();

    // 4) spatial attention
    int smem = (SKR * 65 * 2 + 224 * 2 + 64 * 2 + 128 + 8) * (int)sizeof(float);
    cudaFuncSetAttribute(spatial_attn_kernel,
                         cudaFuncAttributeMaxDynamicSharedMemorySize, smem);
    spatial_attn_kernel<<<BHc * Fc, 256, smem>>>();

    // 5) output GEMM: (25280 x 512) @ (512 x 512) + bias
    dim3 g2(512 / 128, MROWS / 64);
    sgemm64x128<<<g2, 256>>>((const float*)pAO, w_out, b_out, out, MROWS, 512, 512);
}

// round 3
// speedup vs baseline: 1.4702x; 1.4702x over previous
#include <cuda_runtime.h>
#include <math.h>
#include <float.h>

// Problem constants
#define Bc    8
#define Fc    16
#define NSc   196
#define Jc    24
#define Hc    8
#define DHc   64
#define DIMc  512
#define ROTc  32
#define Nc    3160          // J + F*NS
#define MROWS (Bc*Nc)       // 25280
#define BHc   64            // B*H
#define NSP   3136          // F*NS
#define SKR   220           // J + NS (spatial key rows)

// -------- scratch (device globals; no runtime allocation) --------
__device__ float g_qkv[(size_t)MROWS * 1536];     // ~155 MB
__device__ float g_Q   [(size_t)BHc * Nc  * 64];  // scaled (+roped spatial rows)
__device__ float g_Kraw[(size_t)BHc * Nc  * 64];  // un-roped K (joints attn keys)
__device__ float g_Krope[(size_t)BHc * NSP * 64]; // roped spatial K
__device__ float g_V   [(size_t)BHc * Nc  * 64];
__device__ float g_AO  [(size_t)MROWS * 512];     // attention out, (b,n,h*d) layout

// -------- block reduction helpers --------
template<int NW>
__device__ __forceinline__ float block_max(float v, float* red, int tid) {
    #pragma unroll
    for (int o = 16; o; o >>= 1) v = fmaxf(v, __shfl_xor_sync(0xffffffffu, v, o));
    if ((tid & 31) == 0) red[tid >> 5] = v;
    __syncthreads();
    float r = red[0];
    #pragma unroll
    for (int w = 1; w < NW; w++) r = fmaxf(r, red[w]);
    __syncthreads();
    return r;
}

template<int NW>
__device__ __forceinline__ float block_sum(float v, float* red, int tid) {
    #pragma unroll
    for (int o = 16; o; o >>= 1) v += __shfl_xor_sync(0xffffffffu, v, o);
    if ((tid & 31) == 0) red[tid >> 5] = v;
    __syncthreads();
    float r = red[0];
    #pragma unroll
    for (int w = 1; w < NW; w++) r += red[w];
    __syncthreads();
    return r;
}

// -------- tf32 helpers --------
__device__ __forceinline__ unsigned f2tf32(float x) {
    unsigned u;
    asm("cvt.rna.tf32.f32 %0, %1;" : "=r"(u) : "f"(x));
    return u;
}

__device__ __forceinline__ void mma_tf32(float* d, const unsigned* a, const unsigned* b) {
    asm volatile(
        "mma.sync.aligned.m16n8k8.row.col.f32.tf32.tf32.f32 "
        "{%0,%1,%2,%3}, {%4,%5,%6,%7}, {%8,%9}, {%0,%1,%2,%3};\n"
        : "+f"(d[0]), "+f"(d[1]), "+f"(d[2]), "+f"(d[3])
        : "r"(a[0]), "r"(a[1]), "r"(a[2]), "r"(a[3]),
          "r"(b[0]), "r"(b[1]));
}

// -------- TF32 tensor-core GEMM: C[M,N] = A[M,K] @ B[K,N] (+bias) --------
// Block tile 64(M) x 128(N) x 16(K). 256 threads = 8 warps in 2(m) x 4(n) grid,
// each warp computes a 32x32 tile as 2x4 m16n8k8 MMAs per k8 step.
// Requires M%64==0, N%128==0, K%16==0.
__global__ __launch_bounds__(256) void tgemm64x128(
        const float* __restrict__ A, const float* __restrict__ Bm,
        const float* __restrict__ bias, float* __restrict__ C,
        int M, int N, int K) {
    __shared__ unsigned As[64][20];    // [m][k], stride 20 -> conflict-free frag loads
    __shared__ unsigned Bs[16][136];   // [k][n], stride 136 -> conflict-free frag loads

    int tid  = threadIdx.x;
    int lane = tid & 31, warp = tid >> 5;
    int wm = warp >> 2, wn = warp & 3;     // warp grid 2 x 4
    int g  = lane >> 2, t = lane & 3;      // mma quad indices
    int row0 = blockIdx.y * 64;
    int col0 = blockIdx.x * 128;

    // gmem load assignment
    int am  = tid >> 2;             // A row (0..63)
    int ak  = (tid & 3) * 4;        // A k offset (0,4,8,12)
    int bk0 = tid >> 5;             // B k row for first half (0..7)
    int bn  = (tid & 31) * 4;       // B col offset (0..124)

    const float* Ap = A + (size_t)(row0 + am) * K + ak;
    const float* Bp0 = Bm + (size_t)bk0 * N + col0 + bn;
    const float* Bp1 = Bm + (size_t)(bk0 + 8) * N + col0 + bn;

    float acc[2][4][4];
    #pragma unroll
    for (int i = 0; i < 2; i++)
        #pragma unroll
        for (int j = 0; j < 4; j++)
            #pragma unroll
            for (int r = 0; r < 4; r++) acc[i][j][r] = 0.f;

    float4 ra  = *reinterpret_cast<const float4*>(Ap);
    float4 rb0 = *reinterpret_cast<const float4*>(Bp0);
    float4 rb1 = *reinterpret_cast<const float4*>(Bp1);

    for (int k0 = 0; k0 < K; k0 += 16) {
        // store staged tile to smem (tf32-rounded)
        *reinterpret_cast<uint4*>(&As[am][ak]) =
            make_uint4(f2tf32(ra.x), f2tf32(ra.y), f2tf32(ra.z), f2tf32(ra.w));
        *reinterpret_cast<uint4*>(&Bs[bk0][bn]) =
            make_uint4(f2tf32(rb0.x), f2tf32(rb0.y), f2tf32(rb0.z), f2tf32(rb0.w));
        *reinterpret_cast<uint4*>(&Bs[bk0 + 8][bn]) =
            make_uint4(f2tf32(rb1.x), f2tf32(rb1.y), f2tf32(rb1.z), f2tf32(rb1.w));
        __syncthreads();

        // prefetch next gmem tile (overlaps with MMA below)
        if (k0 + 16 < K) {
            Ap  += 16;
            Bp0 += (size_t)16 * N;
            Bp1 += (size_t)16 * N;
            ra  = *reinterpret_cast<const float4*>(Ap);
            rb0 = *reinterpret_cast<const float4*>(Bp0);
            rb1 = *reinterpret_cast<const float4*>(Bp1);
        }

        #pragma unroll
        for (int kk = 0; kk < 16; kk += 8) {
            unsigned af[2][4], bf[4][2];
            #pragma unroll
            for (int i = 0; i < 2; i++) {
                int r = wm * 32 + i * 16;
                af[i][0] = As[r + g][kk + t];
                af[i][1] = As[r + 8 + g][kk + t];
                af[i][2] = As[r + g][kk + 4 + t];
                af[i][3] = As[r + 8 + g][kk + 4 + t];
            }
            #pragma unroll
            for (int j = 0; j < 4; j++) {
                int c = wn * 32 + j * 8 + g;
                bf[j][0] = Bs[kk + t][c];
                bf[j][1] = Bs[kk + 4 + t][c];
            }
            #pragma unroll
            for (int i = 0; i < 2; i++)
                #pragma unroll
                for (int j = 0; j < 4; j++)
                    mma_tf32(acc[i][j], af[i], bf[j]);
        }
        __syncthreads();
    }

    // epilogue
    #pragma unroll
    for (int i = 0; i < 2; i++) {
        #pragma unroll
        for (int j = 0; j < 4; j++) {
            int r = row0 + wm * 32 + i * 16 + g;
            int c = col0 + wn * 32 + j * 8 + 2 * t;
            float bb0 = 0.f, bb1 = 0.f;
            if (bias) { bb0 = bias[c]; bb1 = bias[c + 1]; }
            float2 o0 = make_float2(acc[i][j][0] + bb0, acc[i][j][1] + bb1);
            float2 o1 = make_float2(acc[i][j][2] + bb0, acc[i][j][3] + bb1);
            *reinterpret_cast<float2*>(C + (size_t)r * N + c) = o0;
            *reinterpret_cast<float2*>(C + (size_t)(r + 8) * N + c) = o1;
        }
    }
}

// -------- split qkv into head-major Q/Kraw/Krope/V, apply scale + RoPE --------
__global__ void split_rope_kernel(const float* __restrict__ sinp, const float* __restrict__ cosp) {
    int idx = blockIdx.x * blockDim.x + threadIdx.x;
    const int total = BHc * Nc * 64;
    if (idx >= total) return;
    int d  = idx & 63;
    int n  = (idx >> 6) % Nc;
    int bh = idx / (Nc * 64);
    int b = bh >> 3, h = bh & 7;

    size_t base = ((size_t)b * Nc + n) * 1536 + h * 64;
    float qv = g_qkv[base + d] * 0.125f;       // scale = DH^-0.5 = 1/8
    float kv = g_qkv[base + 512 + d];
    float vv = g_qkv[base + 1024 + d];

    size_t o = ((size_t)bh * Nc + n) * 64 + d;
    g_Kraw[o] = kv;
    g_V[o]    = vv;

    float qo = qv, ko = kv;
    if (n >= Jc) {
        int m = n - Jc;
        int s = m % NSc;
        if (d < ROTc) {
            float c  = cosp[s * ROTc + d];
            float si = sinp[s * ROTc + d];
            if ((d & 1) == 0) {  // out[2i] = t[2i]*cos - t[2i+1]*sin
                float qp = g_qkv[base + d + 1] * 0.125f;
                float kp = g_qkv[base + 512 + d + 1];
                qo = qv * c - qp * si;
                ko = kv * c - kp * si;
            } else {             // out[2i+1] = t[2i+1]*cos + t[2i]*sin
                float qp = g_qkv[base + d - 1] * 0.125f;
                float kp = g_qkv[base + 512 + d - 1];
                qo = qv * c + qp * si;
                ko = kv * c + kp * si;
            }
        }
        g_Krope[((size_t)bh * NSP + m) * 64 + d] = ko;
    }
    g_Q[o] = qo;
}

// -------- joints attention: per (bh, q), softmax over all 3160 un-roped keys --------
__global__ void joints_attn_kernel() {
    int q  = blockIdx.x;   // 0..23
    int bh = blockIdx.y;   // 0..63
    int b = bh >> 3, h = bh & 7;
    __shared__ float sc[Nc];
    __shared__ float qv[64];
    __shared__ float red[8];
    int tid = threadIdx.x; // 128

    const float* Kb = g_Kraw + (size_t)bh * Nc * 64;
    const float* Vb = g_V    + (size_t)bh * Nc * 64;
    if (tid < 64) qv[tid] = g_Q[((size_t)bh * Nc + q) * 64 + tid];
    __syncthreads();

    int lane = tid & 31, warp = tid >> 5;
    for (int j = warp; j < Nc; j += 4) {           // warp per key, coalesced
        const float* kr = Kb + (size_t)j * 64;
        float s = qv[lane] * kr[lane] + qv[lane + 32] * kr[lane + 32];
        #pragma unroll
        for (int o = 16; o; o >>= 1) s += __shfl_xor_sync(0xffffffffu, s, o);
        if (lane == 0) sc[j] = s;
    }
    __syncthreads();

    float mx = -FLT_MAX;
    for (int j = tid; j < Nc; j += 128) mx = fmaxf(mx, sc[j]);
    mx = block_max<4>(mx, red, tid);

    float sum = 0.f;
    for (int j = tid; j < Nc; j += 128) { float e = __expf(sc[j] - mx); sc[j] = e; sum += e; }
    sum = block_sum<4>(sum, red, tid);
    float inv = 1.f / sum;
    __syncthreads();

    // output: 128 threads = 64 dims x 2 key-stripes
    int d = tid & 63, half = tid >> 6;
    float acc = 0.f;
    for (int j = half; j < Nc; j += 2) acc += sc[j] * Vb[(size_t)j * 64 + d];
    __syncthreads();
    if (tid >= 64) qv[d] = acc;
    __syncthreads();
    if (tid < 64) {
        float r = (acc + qv[tid]) * inv;
        g_AO[((size_t)b * Nc + q) * 512 + h * 64 + tid] = r;
    }
}

// -------- spatial attention: per (bh,f): 196 queries over 220 keys (24 joints + 196 roped) --------
__global__ void spatial_attn_kernel() {
    int blk = blockIdx.x;          // 0..1023
    int bh = blk >> 4, f = blk & 15;
    int b = bh >> 3, h = bh & 7;
    extern __shared__ float sm[];
    float* Ks  = sm;               // 220*65
    float* Vs  = Ks  + SKR * 65;   // 220*65
    float* sc0 = Vs  + SKR * 65;   // 224
    float* sc1 = sc0 + 224;        // 224
    float* qv0 = sc1 + 224;        // 64
    float* qv1 = qv0 + 64;         // 64
    float* ob  = qv1 + 64;         // 128
    float* red = ob  + 128;        // 8
    int tid = threadIdx.x;         // 256

    const float* Krb = g_Kraw  + (size_t)bh * Nc  * 64;
    const float* Kpb = g_Krope + (size_t)bh * NSP * 64;
    const float* Vb  = g_V     + (size_t)bh * Nc  * 64;

    for (int i = tid; i < SKR * 64; i += 256) {
        int r = i >> 6, d = i & 63;
        float kv, vv;
        if (r < Jc) { kv = Krb[(size_t)r * 64 + d]; vv = Vb[(size_t)r * 64 + d]; }
        else {
            int m = f * NSc + (r - Jc);
            kv = Kpb[(size_t)m * 64 + d];
            vv = Vb[(size_t)(Jc + m) * 64 + d];
        }
        Ks[r * 65 + d] = kv;
        Vs[r * 65 + d] = vv;
    }
    __syncthreads();

    size_t qrow0 = (size_t)bh * Nc + Jc + f * NSc;
    for (int q0 = 0; q0 < NSc; q0 += 2) {
        if (tid < 64)       qv0[tid]      = g_Q[(qrow0 + q0)     * 64 + tid];
        else if (tid < 128) qv1[tid - 64] = g_Q[(qrow0 + q0 + 1) * 64 + (tid - 64)];
        __syncthreads();

        float s0 = -1e30f, s1 = -1e30f;
        if (tid < SKR) {
            const float* kr = Ks + tid * 65;
            float a0 = 0.f, a1 = 0.f;
            #pragma unroll
            for (int d = 0; d < 64; d++) { float kk = kr[d]; a0 += qv0[d] * kk; a1 += qv1[d] * kk; }
            s0 = a0; s1 = a1;
        }
        float m0 = block_max<8>(s0, red, tid);
        float m1 = block_max<8>(s1, red, tid);
        float e0 = (tid < SKR) ? __expf(s0 - m0) : 0.f;
        float e1 = (tid < SKR) ? __expf(s1 - m1) : 0.f;
        float t0 = block_sum<8>(e0, red, tid);
        float t1 = block_sum<8>(e1, red, tid);
        if (tid < SKR) { sc0[tid] = e0 / t0; sc1[tid] = e1 / t1; }
        __syncthreads();

        // output: 256 threads = 2 queries x 64 dims x 2 key-stripes
        int d = tid & 63, which = (tid >> 6) & 1, half = tid >> 7;
        const float* scp = which ? sc1 : sc0;
        float acc = 0.f;
        for (int j = half; j < SKR; j += 2) acc += scp[j] * Vs[j * 65 + d];
        if (half == 0) ob[tid] = acc;
        __syncthreads();
        if (half == 1) {
            float r = ob[tid - 128] + acc;
            int n = Jc + f * NSc + q0 + which;
            g_AO[((size_t)b * Nc + n) * 512 + h * 64 + d] = r;
        }
        __syncthreads();
    }
}

// -------- launch --------
extern "C" void kernel_launch(void* const* d_in, const int* in_sizes, int n_in,
                              void* d_out, int out_size) {
    const float* x     = (const float*)d_in[0];
    const float* w_qkv = (const float*)d_in[1];
    const float* w_out = (const float*)d_in[2];
    const float* b_out = (const float*)d_in[3];
    const float* sinp  = (const float*)d_in[4];
    const float* cosp  = (const float*)d_in[5];
    float* out = (float*)d_out;

    void *pqkv = nullptr, *pAO = nullptr;
    cudaGetSymbolAddress(&pqkv, g_qkv);
    cudaGetSymbolAddress(&pAO,  g_AO);

    // 1) QKV GEMM: (25280 x 512) @ (512 x 1536) on tensor cores (tf32)
    dim3 g1(1536 / 128, MROWS / 64);
    tgemm64x128<<<g1, 256>>>(x, w_qkv, nullptr, (float*)pqkv, MROWS, 1536, 512);

    // 2) split + scale + RoPE
    int total = BHc * Nc * 64;
    split_rope_kernel<<<(total + 255) / 256, 256>>>(sinp, cosp);

    // 3) joints attention
    joints_attn_kernel<<<dim3(Jc, BHc), 128>>>();

    // 4) spatial attention
    int smem = (SKR * 65 * 2 + 224 * 2 + 64 * 2 + 128 + 8) * (int)sizeof(float);
    cudaFuncSetAttribute(spatial_attn_kernel,
                         cudaFuncAttributeMaxDynamicSharedMemorySize, smem);
    spatial_attn_kernel<<<BHc * Fc, 256, smem>>>();

    // 5) output GEMM: (25280 x 512) @ (512 x 512) + bias on tensor cores (tf32)
    dim3 g2(512 / 128, MROWS / 64);
    tgemm64x128<<<g2, 256>>>((const float*)pAO, w_out, b_out, out, MROWS, 512, 512);
}

// round 4
// speedup vs baseline: 3.0185x; 2.0531x over previous
#include <cuda_runtime.h>
#include <math.h>
#include <float.h>

// Problem constants
#define Bc    8
#define Fc    16
#define NSc   196
#define Jc    24
#define Hc    8
#define DHc   64
#define DIMc  512
#define ROTc  32
#define Nc    3160          // J + F*NS
#define MROWS (Bc*Nc)       // 25280
#define BHc   64            // B*H
#define NSP   3136          // F*NS
#define SKR   220           // J + NS (spatial key rows)

// -------- scratch (device globals; no runtime allocation) --------
__device__ float g_qkv[(size_t)MROWS * 1536];
__device__ float g_Q   [(size_t)BHc * Nc  * 64];
__device__ float g_Kraw[(size_t)BHc * Nc  * 64];
__device__ float g_Krope[(size_t)BHc * NSP * 64];
__device__ float g_V   [(size_t)BHc * Nc  * 64];
__device__ float g_AO  [(size_t)MROWS * 512];

// -------- tf32 helpers --------
__device__ __forceinline__ unsigned f2tf32(float x) {
    unsigned u;
    asm("cvt.rna.tf32.f32 %0, %1;" : "=r"(u) : "f"(x));
    return u;
}

__device__ __forceinline__ void mma_tf32(float* d, const unsigned* a, const unsigned* b) {
    asm volatile(
        "mma.sync.aligned.m16n8k8.row.col.f32.tf32.tf32.f32 "
        "{%0,%1,%2,%3}, {%4,%5,%6,%7}, {%8,%9}, {%0,%1,%2,%3};\n"
        : "+f"(d[0]), "+f"(d[1]), "+f"(d[2]), "+f"(d[3])
        : "r"(a[0]), "r"(a[1]), "r"(a[2]), "r"(a[3]),
          "r"(b[0]), "r"(b[1]));
}

// -------- TF32 tensor-core GEMM: C[M,N] = A[M,K] @ B[K,N] (+bias) --------
__global__ __launch_bounds__(256) void tgemm64x128(
        const float* __restrict__ A, const float* __restrict__ Bm,
        const float* __restrict__ bias, float* __restrict__ C,
        int M, int N, int K) {
    __shared__ unsigned As[64][20];
    __shared__ unsigned Bs[16][136];

    int tid  = threadIdx.x;
    int lane = tid & 31, warp = tid >> 5;
    int wm = warp >> 2, wn = warp & 3;
    int g  = lane >> 2, t = lane & 3;
    int row0 = blockIdx.y * 64;
    int col0 = blockIdx.x * 128;

    int am  = tid >> 2;
    int ak  = (tid & 3) * 4;
    int bk0 = tid >> 5;
    int bn  = (tid & 31) * 4;

    const float* Ap = A + (size_t)(row0 + am) * K + ak;
    const float* Bp0 = Bm + (size_t)bk0 * N + col0 + bn;
    const float* Bp1 = Bm + (size_t)(bk0 + 8) * N + col0 + bn;

    float acc[2][4][4];
    #pragma unroll
    for (int i = 0; i < 2; i++)
        #pragma unroll
        for (int j = 0; j < 4; j++)
            #pragma unroll
            for (int r = 0; r < 4; r++) acc[i][j][r] = 0.f;

    float4 ra  = *reinterpret_cast<const float4*>(Ap);
    float4 rb0 = *reinterpret_cast<const float4*>(Bp0);
    float4 rb1 = *reinterpret_cast<const float4*>(Bp1);

    for (int k0 = 0; k0 < K; k0 += 16) {
        *reinterpret_cast<uint4*>(&As[am][ak]) =
            make_uint4(f2tf32(ra.x), f2tf32(ra.y), f2tf32(ra.z), f2tf32(ra.w));
        *reinterpret_cast<uint4*>(&Bs[bk0][bn]) =
            make_uint4(f2tf32(rb0.x), f2tf32(rb0.y), f2tf32(rb0.z), f2tf32(rb0.w));
        *reinterpret_cast<uint4*>(&Bs[bk0 + 8][bn]) =
            make_uint4(f2tf32(rb1.x), f2tf32(rb1.y), f2tf32(rb1.z), f2tf32(rb1.w));
        __syncthreads();

        if (k0 + 16 < K) {
            Ap  += 16;
            Bp0 += (size_t)16 * N;
            Bp1 += (size_t)16 * N;
            ra  = *reinterpret_cast<const float4*>(Ap);
            rb0 = *reinterpret_cast<const float4*>(Bp0);
            rb1 = *reinterpret_cast<const float4*>(Bp1);
        }

        #pragma unroll
        for (int kk = 0; kk < 16; kk += 8) {
            unsigned af[2][4], bf[4][2];
            #pragma unroll
            for (int i = 0; i < 2; i++) {
                int r = wm * 32 + i * 16;
                af[i][0] = As[r + g][kk + t];
                af[i][1] = As[r + 8 + g][kk + t];
                af[i][2] = As[r + g][kk + 4 + t];
                af[i][3] = As[r + 8 + g][kk + 4 + t];
            }
            #pragma unroll
            for (int j = 0; j < 4; j++) {
                int c = wn * 32 + j * 8 + g;
                bf[j][0] = Bs[kk + t][c];
                bf[j][1] = Bs[kk + 4 + t][c];
            }
            #pragma unroll
            for (int i = 0; i < 2; i++)
                #pragma unroll
                for (int j = 0; j < 4; j++)
                    mma_tf32(acc[i][j], af[i], bf[j]);
        }
        __syncthreads();
    }

    #pragma unroll
    for (int i = 0; i < 2; i++) {
        #pragma unroll
        for (int j = 0; j < 4; j++) {
            int r = row0 + wm * 32 + i * 16 + g;
            int c = col0 + wn * 32 + j * 8 + 2 * t;
            float bb0 = 0.f, bb1 = 0.f;
            if (bias) { bb0 = bias[c]; bb1 = bias[c + 1]; }
            float2 o0 = make_float2(acc[i][j][0] + bb0, acc[i][j][1] + bb1);
            float2 o1 = make_float2(acc[i][j][2] + bb0, acc[i][j][3] + bb1);
            *reinterpret_cast<float2*>(C + (size_t)r * N + c) = o0;
            *reinterpret_cast<float2*>(C + (size_t)(r + 8) * N + c) = o1;
        }
    }
}

// -------- split qkv into head-major Q/Kraw/Krope/V, apply scale + RoPE --------
__global__ void split_rope_kernel(const float* __restrict__ sinp, const float* __restrict__ cosp) {
    int idx = blockIdx.x * blockDim.x + threadIdx.x;
    const int total = BHc * Nc * 64;
    if (idx >= total) return;
    int d  = idx & 63;
    int n  = (idx >> 6) % Nc;
    int bh = idx / (Nc * 64);
    int b = bh >> 3, h = bh & 7;

    size_t base = ((size_t)b * Nc + n) * 1536 + h * 64;
    float qv = g_qkv[base + d] * 0.125f;
    float kv = g_qkv[base + 512 + d];
    float vv = g_qkv[base + 1024 + d];

    size_t o = ((size_t)bh * Nc + n) * 64 + d;
    g_Kraw[o] = kv;
    g_V[o]    = vv;

    float qo = qv, ko = kv;
    if (n >= Jc) {
        int m = n - Jc;
        int s = m % NSc;
        if (d < ROTc) {
            float c  = cosp[s * ROTc + d];
            float si = sinp[s * ROTc + d];
            if ((d & 1) == 0) {
                float qp = g_qkv[base + d + 1] * 0.125f;
                float kp = g_qkv[base + 512 + d + 1];
                qo = qv * c - qp * si;
                ko = kv * c - kp * si;
            } else {
                float qp = g_qkv[base + d - 1] * 0.125f;
                float kp = g_qkv[base + 512 + d - 1];
                qo = qv * c + qp * si;
                ko = kv * c + kp * si;
            }
        }
        g_Krope[((size_t)bh * NSP + m) * 64 + d] = ko;
    }
    g_Q[o] = qo;
}

// ============ joints attention (flash, tf32 MMA): block per bh ============
// S^T[128,32] = Kchunk[128,64] @ Qt[64,32]; online softmax; O += P@V.
__global__ __launch_bounds__(256) void joints_attn_mma() {
    extern __shared__ float smem[];
    unsigned* uK = (unsigned*)smem;           // 128*68
    unsigned* uV = uK + 128 * 68;             // 128*68
    unsigned* uQ = uV + 128 * 68;             // 64*36
    float*    St = (float*)(uQ + 64 * 36);    // 128*36
    unsigned* uP = (unsigned*)(St + 128 * 36);// 32*133
    float*   red = (float*)(uP + 32 * 133);   // 256
    float*  mrow = red + 256;                 // 32
    float*   scl = mrow + 32;                 // 32
    float*  lrow = scl + 32;                  // 32

    int bh = blockIdx.x;
    int b = bh >> 3, h = bh & 7;
    int tid = threadIdx.x, lane = tid & 31, warp = tid >> 5;
    int g = lane >> 2, t = lane & 3;

    const float* Kb = g_Kraw + (size_t)bh * Nc * 64;
    const float* Vb = g_V    + (size_t)bh * Nc * 64;

    if (tid < 32) { mrow[tid] = -FLT_MAX; lrow[tid] = 0.f; }

    for (int i = tid; i < 32 * 64; i += 256) {
        int q = i >> 6, d = i & 63;
        int qq = (q < Jc) ? q : (Jc - 1);
        uQ[d * 36 + q] = f2tf32(g_Q[((size_t)bh * Nc + qq) * 64 + d]);
    }

    float oc[2][4] = {{0,0,0,0},{0,0,0,0}};

    for (int c0 = 0; c0 < Nc; c0 += 128) {
        int kn = min(128, Nc - c0);
        __syncthreads();
        for (int i = tid; i < kn * 64; i += 256) {
            int r = i >> 6, d = i & 63;
            uK[r * 68 + d] = f2tf32(Kb[(size_t)(c0 + r) * 64 + d]);
            uV[r * 68 + d] = f2tf32(Vb[(size_t)(c0 + r) * 64 + d]);
        }
        __syncthreads();

        // S^T MMA: 8 m-tiles x 4 n-tiles
        for (int tIdx = warp; tIdx < 32; tIdx += 8) {
            int mi = tIdx & 7, ni = tIdx >> 3;
            float c[4] = {0,0,0,0};
            #pragma unroll
            for (int kk = 0; kk < 8; kk++) {
                unsigned a[4], bfr[2];
                const unsigned* Ab = uK + (mi * 16) * 68 + kk * 8;
                a[0] = Ab[g * 68 + t];       a[1] = Ab[(g + 8) * 68 + t];
                a[2] = Ab[g * 68 + 4 + t];   a[3] = Ab[(g + 8) * 68 + 4 + t];
                const unsigned* Bb = uQ + (kk * 8) * 36 + ni * 8;
                bfr[0] = Bb[t * 36 + g];     bfr[1] = Bb[(4 + t) * 36 + g];
                mma_tf32(c, a, bfr);
            }
            float* Sb = St + (mi * 16) * 36 + ni * 8;
            *(float2*)(Sb + g * 36 + 2 * t)       = make_float2(c[0], c[1]);
            *(float2*)(Sb + (g + 8) * 36 + 2 * t) = make_float2(c[2], c[3]);
        }
        __syncthreads();

        // online softmax update
        {
            int q = tid & 31, s = tid >> 5;
            int j0 = s * 16, j1 = min(j0 + 16, kn);
            float lm = -FLT_MAX;
            for (int j = j0; j < j1; j++) lm = fmaxf(lm, St[j * 36 + q]);
            red[s * 32 + q] = lm;
            __syncthreads();
            float cm = red[q];
            #pragma unroll
            for (int ss = 1; ss < 8; ss++) cm = fmaxf(cm, red[ss * 32 + q]);
            float mold = mrow[q];
            float mnew = fmaxf(mold, cm);
            __syncthreads();
            float ls = 0.f;
            for (int j = j0; j < j1; j++) {
                float e = __expf(St[j * 36 + q] - mnew);
                ls += e;
                uP[q * 133 + j] = f2tf32(e);
            }
            for (int j = j1; j < j0 + 16; j++) uP[q * 133 + j] = 0u;
            red[s * 32 + q] = ls;
            __syncthreads();
            if (s == 0) {
                float tot = 0.f;
                #pragma unroll
                for (int ss = 0; ss < 8; ss++) tot += red[ss * 32 + q];
                float sc = __expf(mold - mnew);
                lrow[q] = lrow[q] * sc + tot;
                mrow[q] = mnew;
                scl[q]  = sc;
            }
        }
        __syncthreads();

        // rescale + accumulate O += P @ V  (2 tiles per warp: 2m x 8n grid)
        #pragma unroll
        for (int ti = 0; ti < 2; ti++) {
            int tIdx = warp + ti * 8;
            int mi = tIdx & 1, ni = tIdx >> 1;
            int q = mi * 16 + g;
            float s0 = scl[q], s1 = scl[q + 8];
            oc[ti][0] *= s0; oc[ti][1] *= s0; oc[ti][2] *= s1; oc[ti][3] *= s1;
            for (int kk = 0; kk < 16; kk++) {
                unsigned a[4], bfr[2];
                const unsigned* Ab = uP + (mi * 16) * 133 + kk * 8;
                a[0] = Ab[g * 133 + t];      a[1] = Ab[(g + 8) * 133 + t];
                a[2] = Ab[g * 133 + 4 + t];  a[3] = Ab[(g + 8) * 133 + 4 + t];
                const unsigned* Bb = uV + (kk * 8) * 68 + ni * 8;
                bfr[0] = Bb[t * 68 + g];     bfr[1] = Bb[(4 + t) * 68 + g];
                mma_tf32(oc[ti], a, bfr);
            }
        }
    }
    __syncthreads();

    #pragma unroll
    for (int ti = 0; ti < 2; ti++) {
        int tIdx = warp + ti * 8;
        int mi = tIdx & 1, ni = tIdx >> 1;
        int q = mi * 16 + g, d = ni * 8 + 2 * t;
        if (q < Jc) {
            float inv = 1.f / lrow[q];
            *(float2*)(g_AO + ((size_t)b * Nc + q) * 512 + h * 64 + d) =
                make_float2(oc[ti][0] * inv, oc[ti][1] * inv);
        }
        if (q + 8 < Jc) {
            float inv = 1.f / lrow[q + 8];
            *(float2*)(g_AO + ((size_t)b * Nc + q + 8) * 512 + h * 64 + d) =
                make_float2(oc[ti][2] * inv, oc[ti][3] * inv);
        }
    }
}

// ============ spatial attention (tf32 MMA): block per (bh,f) ============
// K/V resident in smem (224 rows incl 4 zero-pad); loop 7 q-tiles of 32.
__global__ __launch_bounds__(256) void spatial_attn_mma() {
    extern __shared__ float smem[];
    unsigned* uK = (unsigned*)smem;             // 224*68
    unsigned* uV = uK + 224 * 68;               // 224*68
    unsigned* uQ = uV + 224 * 68;               // 64*36
    float*    St = (float*)(uQ + 64 * 36);      // 224*36
    unsigned* uP = (unsigned*)(St + 224 * 36);  // 32*233
    float*   red = (float*)(uP + 32 * 233);     // 256
    float*  srow = red + 256;                   // 32

    int blk = blockIdx.x;
    int bh = blk >> 4, f = blk & 15;
    int b = bh >> 3, h = bh & 7;
    int tid = threadIdx.x, lane = tid & 31, warp = tid >> 5;
    int g = lane >> 2, t = lane & 3;

    const float* Krb = g_Kraw  + (size_t)bh * Nc  * 64;
    const float* Kpb = g_Krope + (size_t)bh * NSP * 64;
    const float* Vb  = g_V     + (size_t)bh * Nc  * 64;

    for (int i = tid; i < 224 * 64; i += 256) {
        int r = i >> 6, d = i & 63;
        float kv = 0.f, vv = 0.f;
        if (r < Jc) { kv = Krb[r * 64 + d]; vv = Vb[r * 64 + d]; }
        else if (r < SKR) {
            int m = f * NSc + (r - Jc);
            kv = Kpb[(size_t)m * 64 + d];
            vv = Vb[(size_t)(Jc + m) * 64 + d];
        }
        uK[r * 68 + d] = f2tf32(kv);
        uV[r * 68 + d] = f2tf32(vv);
    }
    size_t qrow0 = (size_t)bh * Nc + Jc + f * NSc;
    __syncthreads();

    for (int q0 = 0; q0 < NSc; q0 += 32) {
        for (int i = tid; i < 32 * 64; i += 256) {
            int q = i >> 6, d = i & 63;
            int qq = q0 + q; if (qq > NSc - 1) qq = NSc - 1;
            uQ[d * 36 + q] = f2tf32(g_Q[(qrow0 + qq) * 64 + d]);
        }
        __syncthreads();

        // S^T = K @ Qt : 14 m-tiles x 4 n-tiles = 56 tiles
        for (int tIdx = warp; tIdx < 56; tIdx += 8) {
            int mi = tIdx % 14, ni = tIdx / 14;
            float c[4] = {0,0,0,0};
            #pragma unroll
            for (int kk = 0; kk < 8; kk++) {
                unsigned a[4], bfr[2];
                const unsigned* Ab = uK + (mi * 16) * 68 + kk * 8;
                a[0] = Ab[g * 68 + t];       a[1] = Ab[(g + 8) * 68 + t];
                a[2] = Ab[g * 68 + 4 + t];   a[3] = Ab[(g + 8) * 68 + 4 + t];
                const unsigned* Bb = uQ + (kk * 8) * 36 + ni * 8;
                bfr[0] = Bb[t * 36 + g];     bfr[1] = Bb[(4 + t) * 36 + g];
                mma_tf32(c, a, bfr);
            }
            float* Sb = St + (mi * 16) * 36 + ni * 8;
            *(float2*)(Sb + g * 36 + 2 * t)       = make_float2(c[0], c[1]);
            *(float2*)(Sb + (g + 8) * 36 + 2 * t) = make_float2(c[2], c[3]);
        }
        __syncthreads();

        // softmax (per q over 220 keys), write unnormalized exp to uP, 1/sum in srow
        {
            int q = tid & 31, s = tid >> 5;
            int j0 = s * 28, j1 = min(j0 + 28, SKR);
            float lm = -FLT_MAX;
            for (int j = j0; j < j1; j++) lm = fmaxf(lm, St[j * 36 + q]);
            red[s * 32 + q] = lm;
            __syncthreads();
            float m = red[q];
            #pragma unroll
            for (int ss = 1; ss < 8; ss++) m = fmaxf(m, red[ss * 32 + q]);
            __syncthreads();
            float ls = 0.f;
            for (int j = j0; j < j1; j++) {
                float e = __expf(St[j * 36 + q] - m);
                ls += e;
                uP[q * 233 + j] = f2tf32(e);
            }
            if (s == 7) for (int j = SKR; j < 224; j++) uP[q * 233 + j] = 0u;
            red[s * 32 + q] = ls;
            __syncthreads();
            if (s == 0) {
                float tot = 0.f;
                #pragma unroll
                for (int ss = 0; ss < 8; ss++) tot += red[ss * 32 + q];
                srow[q] = 1.f / tot;
            }
        }
        __syncthreads();

        // O = P @ V : 2 m-tiles x 8 n-tiles
        for (int tIdx = warp; tIdx < 16; tIdx += 8) {
            int mi = tIdx & 1, ni = tIdx >> 1;
            float c[4] = {0,0,0,0};
            for (int kk = 0; kk < 28; kk++) {
                unsigned a[4], bfr[2];
                const unsigned* Ab = uP + (mi * 16) * 233 + kk * 8;
                a[0] = Ab[g * 233 + t];      a[1] = Ab[(g + 8) * 233 + t];
                a[2] = Ab[g * 233 + 4 + t];  a[3] = Ab[(g + 8) * 233 + 4 + t];
                const unsigned* Bb = uV + (kk * 8) * 68 + ni * 8;
                bfr[0] = Bb[t * 68 + g];     bfr[1] = Bb[(4 + t) * 68 + g];
                mma_tf32(c, a, bfr);
            }
            int q = mi * 16 + g, d = ni * 8 + 2 * t;
            int qq = q0 + q;
            if (qq < NSc) {
                float inv = srow[q];
                int n = Jc + f * NSc + qq;
                *(float2*)(g_AO + ((size_t)b * Nc + n) * 512 + h * 64 + d) =
                    make_float2(c[0] * inv, c[1] * inv);
            }
            if (qq + 8 < NSc) {
                float inv = srow[q + 8];
                int n = Jc + f * NSc + qq + 8;
                *(float2*)(g_AO + ((size_t)b * Nc + n) * 512 + h * 64 + d) =
                    make_float2(c[2] * inv, c[3] * inv);
            }
        }
        __syncthreads();
    }
}

// -------- launch --------
extern "C" void kernel_launch(void* const* d_in, const int* in_sizes, int n_in,
                              void* d_out, int out_size) {
    const float* x     = (const float*)d_in[0];
    const float* w_qkv = (const float*)d_in[1];
    const float* w_out = (const float*)d_in[2];
    const float* b_out = (const float*)d_in[3];
    const float* sinp  = (const float*)d_in[4];
    const float* cosp  = (const float*)d_in[5];
    float* out = (float*)d_out;

    void *pqkv = nullptr, *pAO = nullptr;
    cudaGetSymbolAddress(&pqkv, g_qkv);
    cudaGetSymbolAddress(&pAO,  g_AO);

    const int JSMEM = (128*68*2 + 64*36 + 128*36 + 32*133 + 256 + 96) * 4;
    const int SSMEM = (224*68*2 + 64*36 + 224*36 + 32*233 + 256 + 32) * 4;
    cudaFuncSetAttribute(joints_attn_mma,
                         cudaFuncAttributeMaxDynamicSharedMemorySize, JSMEM);
    cudaFuncSetAttribute(spatial_attn_mma,
                         cudaFuncAttributeMaxDynamicSharedMemorySize, SSMEM);

    // 1) QKV GEMM
    dim3 g1(1536 / 128, MROWS / 64);
    tgemm64x128<<<g1, 256>>>(x, w_qkv, nullptr, (float*)pqkv, MROWS, 1536, 512);

    // 2) split + scale + RoPE
    int total = BHc * Nc * 64;
    split_rope_kernel<<<(total + 255) / 256, 256>>>(sinp, cosp);

    // 3) joints attention (flash MMA)
    joints_attn_mma<<<BHc, 256, JSMEM>>>();

    // 4) spatial attention (MMA)
    spatial_attn_mma<<<BHc * Fc, 256, SSMEM>>>();

    // 5) output GEMM
    dim3 g2(512 / 128, MROWS / 64);
    tgemm64x128<<<g2, 256>>>((const float*)pAO, w_out, b_out, out, MROWS, 512, 512);
}

// round 5
// speedup vs baseline: 3.0228x; 1.0014x over previous
#include <cuda_runtime.h>
#include <math.h>
#include <float.h>

// Problem constants
#define Bc    8
#define Fc    16
#define NSc   196
#define Jc    24
#define Hc    8
#define DHc   64
#define DIMc  512
#define ROTc  32
#define Nc    3160          // J + F*NS
#define MROWS (Bc*Nc)       // 25280
#define BHc   64            // B*H
#define NSP   3136          // F*NS
#define SKR   220           // J + NS (spatial key rows)

// -------- scratch (device globals; no runtime allocation) --------
__device__ float g_qkv[(size_t)MROWS * 1536];
__device__ float g_Q   [(size_t)BHc * Nc  * 64];
__device__ float g_Kraw[(size_t)BHc * Nc  * 64];
__device__ float g_Krope[(size_t)BHc * NSP * 64];
__device__ float g_V   [(size_t)BHc * Nc  * 64];
__device__ float g_AO  [(size_t)MROWS * 512];

// -------- tf32 helpers --------
__device__ __forceinline__ unsigned f2tf32(float x) {
    unsigned u;
    asm("cvt.rna.tf32.f32 %0, %1;" : "=r"(u) : "f"(x));
    return u;
}

__device__ __forceinline__ void mma_tf32(float* d, const unsigned* a, const unsigned* b) {
    asm volatile(
        "mma.sync.aligned.m16n8k8.row.col.f32.tf32.tf32.f32 "
        "{%0,%1,%2,%3}, {%4,%5,%6,%7}, {%8,%9}, {%0,%1,%2,%3};\n"
        : "+f"(d[0]), "+f"(d[1]), "+f"(d[2]), "+f"(d[3])
        : "r"(a[0]), "r"(a[1]), "r"(a[2]), "r"(a[3]),
          "r"(b[0]), "r"(b[1]));
}

// -------- TF32 tensor-core GEMM: C[M,N] = A[M,K] @ B[K,N] (+bias) --------
__global__ __launch_bounds__(256) void tgemm64x128(
        const float* __restrict__ A, const float* __restrict__ Bm,
        const float* __restrict__ bias, float* __restrict__ C,
        int M, int N, int K) {
    __shared__ unsigned As[64][20];
    __shared__ unsigned Bs[16][136];

    int tid  = threadIdx.x;
    int lane = tid & 31, warp = tid >> 5;
    int wm = warp >> 2, wn = warp & 3;
    int g  = lane >> 2, t = lane & 3;
    int row0 = blockIdx.y * 64;
    int col0 = blockIdx.x * 128;

    int am  = tid >> 2;
    int ak  = (tid & 3) * 4;
    int bk0 = tid >> 5;
    int bn  = (tid & 31) * 4;

    const float* Ap = A + (size_t)(row0 + am) * K + ak;
    const float* Bp0 = Bm + (size_t)bk0 * N + col0 + bn;
    const float* Bp1 = Bm + (size_t)(bk0 + 8) * N + col0 + bn;

    float acc[2][4][4];
    #pragma unroll
    for (int i = 0; i < 2; i++)
        #pragma unroll
        for (int j = 0; j < 4; j++)
            #pragma unroll
            for (int r = 0; r < 4; r++) acc[i][j][r] = 0.f;

    float4 ra  = *reinterpret_cast<const float4*>(Ap);
    float4 rb0 = *reinterpret_cast<const float4*>(Bp0);
    float4 rb1 = *reinterpret_cast<const float4*>(Bp1);

    for (int k0 = 0; k0 < K; k0 += 16) {
        *reinterpret_cast<uint4*>(&As[am][ak]) =
            make_uint4(f2tf32(ra.x), f2tf32(ra.y), f2tf32(ra.z), f2tf32(ra.w));
        *reinterpret_cast<uint4*>(&Bs[bk0][bn]) =
            make_uint4(f2tf32(rb0.x), f2tf32(rb0.y), f2tf32(rb0.z), f2tf32(rb0.w));
        *reinterpret_cast<uint4*>(&Bs[bk0 + 8][bn]) =
            make_uint4(f2tf32(rb1.x), f2tf32(rb1.y), f2tf32(rb1.z), f2tf32(rb1.w));
        __syncthreads();

        if (k0 + 16 < K) {
            Ap  += 16;
            Bp0 += (size_t)16 * N;
            Bp1 += (size_t)16 * N;
            ra  = *reinterpret_cast<const float4*>(Ap);
            rb0 = *reinterpret_cast<const float4*>(Bp0);
            rb1 = *reinterpret_cast<const float4*>(Bp1);
        }

        #pragma unroll
        for (int kk = 0; kk < 16; kk += 8) {
            unsigned af[2][4], bf[4][2];
            #pragma unroll
            for (int i = 0; i < 2; i++) {
                int r = wm * 32 + i * 16;
                af[i][0] = As[r + g][kk + t];
                af[i][1] = As[r + 8 + g][kk + t];
                af[i][2] = As[r + g][kk + 4 + t];
                af[i][3] = As[r + 8 + g][kk + 4 + t];
            }
            #pragma unroll
            for (int j = 0; j < 4; j++) {
                int c = wn * 32 + j * 8 + g;
                bf[j][0] = Bs[kk + t][c];
                bf[j][1] = Bs[kk + 4 + t][c];
            }
            #pragma unroll
            for (int i = 0; i < 2; i++)
                #pragma unroll
                for (int j = 0; j < 4; j++)
                    mma_tf32(acc[i][j], af[i], bf[j]);
        }
        __syncthreads();
    }

    #pragma unroll
    for (int i = 0; i < 2; i++) {
        #pragma unroll
        for (int j = 0; j < 4; j++) {
            int r = row0 + wm * 32 + i * 16 + g;
            int c = col0 + wn * 32 + j * 8 + 2 * t;
            float bb0 = 0.f, bb1 = 0.f;
            if (bias) { bb0 = bias[c]; bb1 = bias[c + 1]; }
            float2 o0 = make_float2(acc[i][j][0] + bb0, acc[i][j][1] + bb1);
            float2 o1 = make_float2(acc[i][j][2] + bb0, acc[i][j][3] + bb1);
            *reinterpret_cast<float2*>(C + (size_t)r * N + c) = o0;
            *reinterpret_cast<float2*>(C + (size_t)(r + 8) * N + c) = o1;
        }
    }
}

// -------- split qkv into head-major Q/Kraw/Krope/V, apply scale + RoPE --------
__global__ void split_rope_kernel(const float* __restrict__ sinp, const float* __restrict__ cosp) {
    int idx = blockIdx.x * blockDim.x + threadIdx.x;
    const int total = BHc * Nc * 64;
    if (idx >= total) return;
    int d  = idx & 63;
    int n  = (idx >> 6) % Nc;
    int bh = idx / (Nc * 64);
    int b = bh >> 3, h = bh & 7;

    size_t base = ((size_t)b * Nc + n) * 1536 + h * 64;
    float qv = g_qkv[base + d] * 0.125f;
    float kv = g_qkv[base + 512 + d];
    float vv = g_qkv[base + 1024 + d];

    size_t o = ((size_t)bh * Nc + n) * 64 + d;
    g_Kraw[o] = kv;
    g_V[o]    = vv;

    float qo = qv, ko = kv;
    if (n >= Jc) {
        int m = n - Jc;
        int s = m % NSc;
        if (d < ROTc) {
            float c  = cosp[s * ROTc + d];
            float si = sinp[s * ROTc + d];
            if ((d & 1) == 0) {
                float qp = g_qkv[base + d + 1] * 0.125f;
                float kp = g_qkv[base + 512 + d + 1];
                qo = qv * c - qp * si;
                ko = kv * c - kp * si;
            } else {
                float qp = g_qkv[base + d - 1] * 0.125f;
                float kp = g_qkv[base + 512 + d - 1];
                qo = qv * c + qp * si;
                ko = kv * c + kp * si;
            }
        }
        g_Krope[((size_t)bh * NSP + m) * 64 + d] = ko;
    }
    g_Q[o] = qo;
}

// ============ joints attention (flash, tf32 MMA): block per bh ============
// S^T[128,32] = Kchunk[128,64] @ Qt[64,32]; online softmax; O += P@V.
__global__ __launch_bounds__(256) void joints_attn_mma() {
    extern __shared__ float smem[];
    unsigned* uK = (unsigned*)smem;           // 128*68
    unsigned* uV = uK + 128 * 68;             // 128*68
    unsigned* uQ = uV + 128 * 68;             // 64*36
    float*    St = (float*)(uQ + 64 * 36);    // 128*36
    unsigned* uP = (unsigned*)(St + 128 * 36);// 32*133
    float*   red = (float*)(uP + 32 * 133);   // 256
    float*  mrow = red + 256;                 // 32
    float*   scl = mrow + 32;                 // 32
    float*  lrow = scl + 32;                  // 32

    int bh = blockIdx.x;
    int b = bh >> 3, h = bh & 7;
    int tid = threadIdx.x, lane = tid & 31, warp = tid >> 5;
    int g = lane >> 2, t = lane & 3;

    const float* Kb = g_Kraw + (size_t)bh * Nc * 64;
    const float* Vb = g_V    + (size_t)bh * Nc * 64;

    if (tid < 32) { mrow[tid] = -FLT_MAX; lrow[tid] = 0.f; }

    for (int i = tid; i < 32 * 64; i += 256) {
        int q = i >> 6, d = i & 63;
        int qq = (q < Jc) ? q : (Jc - 1);
        uQ[d * 36 + q] = f2tf32(g_Q[((size_t)bh * Nc + qq) * 64 + d]);
    }

    float oc[2][4] = {{0,0,0,0},{0,0,0,0}};

    for (int c0 = 0; c0 < Nc; c0 += 128) {
        int kn = min(128, Nc - c0);
        __syncthreads();
        for (int i = tid; i < kn * 64; i += 256) {
            int r = i >> 6, d = i & 63;
            uK[r * 68 + d] = f2tf32(Kb[(size_t)(c0 + r) * 64 + d]);
            uV[r * 68 + d] = f2tf32(Vb[(size_t)(c0 + r) * 64 + d]);
        }
        __syncthreads();

        // S^T MMA: 8 m-tiles x 4 n-tiles
        for (int tIdx = warp; tIdx < 32; tIdx += 8) {
            int mi = tIdx & 7, ni = tIdx >> 3;
            float c[4] = {0,0,0,0};
            #pragma unroll
            for (int kk = 0; kk < 8; kk++) {
                unsigned a[4], bfr[2];
                const unsigned* Ab = uK + (mi * 16) * 68 + kk * 8;
                a[0] = Ab[g * 68 + t];       a[1] = Ab[(g + 8) * 68 + t];
                a[2] = Ab[g * 68 + 4 + t];   a[3] = Ab[(g + 8) * 68 + 4 + t];
                const unsigned* Bb = uQ + (kk * 8) * 36 + ni * 8;
                bfr[0] = Bb[t * 36 + g];     bfr[1] = Bb[(4 + t) * 36 + g];
                mma_tf32(c, a, bfr);
            }
            float* Sb = St + (mi * 16) * 36 + ni * 8;
            *(float2*)(Sb + g * 36 + 2 * t)       = make_float2(c[0], c[1]);
            *(float2*)(Sb + (g + 8) * 36 + 2 * t) = make_float2(c[2], c[3]);
        }
        __syncthreads();

        // online softmax update
        {
            int q = tid & 31, s = tid >> 5;
            int j0 = s * 16, j1 = min(j0 + 16, kn);
            float lm = -FLT_MAX;
            for (int j = j0; j < j1; j++) lm = fmaxf(lm, St[j * 36 + q]);
            red[s * 32 + q] = lm;
            __syncthreads();
            float cm = red[q];
            #pragma unroll
            for (int ss = 1; ss < 8; ss++) cm = fmaxf(cm, red[ss * 32 + q]);
            float mold = mrow[q];
            float mnew = fmaxf(mold, cm);
            __syncthreads();
            float ls = 0.f;
            for (int j = j0; j < j1; j++) {
                float e = __expf(St[j * 36 + q] - mnew);
                ls += e;
                uP[q * 133 + j] = f2tf32(e);
            }
            for (int j = j1; j < j0 + 16; j++) uP[q * 133 + j] = 0u;
            red[s * 32 + q] = ls;
            __syncthreads();
            if (s == 0) {
                float tot = 0.f;
                #pragma unroll
                for (int ss = 0; ss < 8; ss++) tot += red[ss * 32 + q];
                float sc = __expf(mold - mnew);
                lrow[q] = lrow[q] * sc + tot;
                mrow[q] = mnew;
                scl[q]  = sc;
            }
        }
        __syncthreads();

        // rescale + accumulate O += P @ V  (2 tiles per warp: 2m x 8n grid)
        #pragma unroll
        for (int ti = 0; ti < 2; ti++) {
            int tIdx = warp + ti * 8;
            int mi = tIdx & 1, ni = tIdx >> 1;
            int q = mi * 16 + g;
            float s0 = scl[q], s1 = scl[q + 8];
            oc[ti][0] *= s0; oc[ti][1] *= s0; oc[ti][2] *= s1; oc[ti][3] *= s1;
            for (int kk = 0; kk < 16; kk++) {
                unsigned a[4], bfr[2];
                const unsigned* Ab = uP + (mi * 16) * 133 + kk * 8;
                a[0] = Ab[g * 133 + t];      a[1] = Ab[(g + 8) * 133 + t];
                a[2] = Ab[g * 133 + 4 + t];  a[3] = Ab[(g + 8) * 133 + 4 + t];
                const unsigned* Bb = uV + (kk * 8) * 68 + ni * 8;
                bfr[0] = Bb[t * 68 + g];     bfr[1] = Bb[(4 + t) * 68 + g];
                mma_tf32(oc[ti], a, bfr);
            }
        }
    }
    __syncthreads();

    #pragma unroll
    for (int ti = 0; ti < 2; ti++) {
        int tIdx = warp + ti * 8;
        int mi = tIdx & 1, ni = tIdx >> 1;
        int q = mi * 16 + g, d = ni * 8 + 2 * t;
        if (q < Jc) {
            float inv = 1.f / lrow[q];
            *(float2*)(g_AO + ((size_t)b * Nc + q) * 512 + h * 64 + d) =
                make_float2(oc[ti][0] * inv, oc[ti][1] * inv);
        }
        if (q + 8 < Jc) {
            float inv = 1.f / lrow[q + 8];
            *(float2*)(g_AO + ((size_t)b * Nc + q + 8) * 512 + h * 64 + d) =
                make_float2(oc[ti][2] * inv, oc[ti][3] * inv);
        }
    }
}

// ============ spatial attention (tf32 MMA): block per (bh,f) ============
// K/V resident in smem (224 rows incl 4 zero-pad); loop 7 q-tiles of 32.
__global__ __launch_bounds__(256) void spatial_attn_mma() {
    extern __shared__ float smem[];
    unsigned* uK = (unsigned*)smem;             // 224*68
    unsigned* uV = uK + 224 * 68;               // 224*68
    unsigned* uQ = uV + 224 * 68;               // 64*36
    float*    St = (float*)(uQ + 64 * 36);      // 224*36
    unsigned* uP = (unsigned*)(St + 224 * 36);  // 32*233
    float*   red = (float*)(uP + 32 * 233);     // 256
    float*  srow = red + 256;                   // 32

    int blk = blockIdx.x;
    int bh = blk >> 4, f = blk & 15;
    int b = bh >> 3, h = bh & 7;
    int tid = threadIdx.x, lane = tid & 31, warp = tid >> 5;
    int g = lane >> 2, t = lane & 3;

    const float* Krb = g_Kraw  + (size_t)bh * Nc  * 64;
    const float* Kpb = g_Krope + (size_t)bh * NSP * 64;
    const float* Vb  = g_V     + (size_t)bh * Nc  * 64;

    for (int i = tid; i < 224 * 64; i += 256) {
        int r = i >> 6, d = i & 63;
        float kv = 0.f, vv = 0.f;
        if (r < Jc) { kv = Krb[r * 64 + d]; vv = Vb[r * 64 + d]; }
        else if (r < SKR) {
            int m = f * NSc + (r - Jc);
            kv = Kpb[(size_t)m * 64 + d];
            vv = Vb[(size_t)(Jc + m) * 64 + d];
        }
        uK[r * 68 + d] = f2tf32(kv);
        uV[r * 68 + d] = f2tf32(vv);
    }
    size_t qrow0 = (size_t)bh * Nc + Jc + f * NSc;
    __syncthreads();

    for (int q0 = 0; q0 < NSc; q0 += 32) {
        for (int i = tid; i < 32 * 64; i += 256) {
            int q = i >> 6, d = i & 63;
            int qq = q0 + q; if (qq > NSc - 1) qq = NSc - 1;
            uQ[d * 36 + q] = f2tf32(g_Q[(qrow0 + qq) * 64 + d]);
        }
        __syncthreads();

        // S^T = K @ Qt : 14 m-tiles x 4 n-tiles = 56 tiles
        for (int tIdx = warp; tIdx < 56; tIdx += 8) {
            int mi = tIdx % 14, ni = tIdx / 14;
            float c[4] = {0,0,0,0};
            #pragma unroll
            for (int kk = 0; kk < 8; kk++) {
                unsigned a[4], bfr[2];
                const unsigned* Ab = uK + (mi * 16) * 68 + kk * 8;
                a[0] = Ab[g * 68 + t];       a[1] = Ab[(g + 8) * 68 + t];
                a[2] = Ab[g * 68 + 4 + t];   a[3] = Ab[(g + 8) * 68 + 4 + t];
                const unsigned* Bb = uQ + (kk * 8) * 36 + ni * 8;
                bfr[0] = Bb[t * 36 + g];     bfr[1] = Bb[(4 + t) * 36 + g];
                mma_tf32(c, a, bfr);
            }
            float* Sb = St + (mi * 16) * 36 + ni * 8;
            *(float2*)(Sb + g * 36 + 2 * t)       = make_float2(c[0], c[1]);
            *(float2*)(Sb + (g + 8) * 36 + 2 * t) = make_float2(c[2], c[3]);
        }
        __syncthreads();

        // softmax (per q over 220 keys), write unnormalized exp to uP, 1/sum in srow
        {
            int q = tid & 31, s = tid >> 5;
            int j0 = s * 28, j1 = min(j0 + 28, SKR);
            float lm = -FLT_MAX;
            for (int j = j0; j < j1; j++) lm = fmaxf(lm, St[j * 36 + q]);
            red[s * 32 + q] = lm;
            __syncthreads();
            float m = red[q];
            #pragma unroll
            for (int ss = 1; ss < 8; ss++) m = fmaxf(m, red[ss * 32 + q]);
            __syncthreads();
            float ls = 0.f;
            for (int j = j0; j < j1; j++) {
                float e = __expf(St[j * 36 + q] - m);
                ls += e;
                uP[q * 233 + j] = f2tf32(e);
            }
            if (s == 7) for (int j = SKR; j < 224; j++) uP[q * 233 + j] = 0u;
            red[s * 32 + q] = ls;
            __syncthreads();
            if (s == 0) {
                float tot = 0.f;
                #pragma unroll
                for (int ss = 0; ss < 8; ss++) tot += red[ss * 32 + q];
                srow[q] = 1.f / tot;
            }
        }
        __syncthreads();

        // O = P @ V : 2 m-tiles x 8 n-tiles
        for (int tIdx = warp; tIdx < 16; tIdx += 8) {
            int mi = tIdx & 1, ni = tIdx >> 1;
            float c[4] = {0,0,0,0};
            for (int kk = 0; kk < 28; kk++) {
                unsigned a[4], bfr[2];
                const unsigned* Ab = uP + (mi * 16) * 233 + kk * 8;
                a[0] = Ab[g * 233 + t];      a[1] = Ab[(g + 8) * 233 + t];
                a[2] = Ab[g * 233 + 4 + t];  a[3] = Ab[(g + 8) * 233 + 4 + t];
                const unsigned* Bb = uV + (kk * 8) * 68 + ni * 8;
                bfr[0] = Bb[t * 68 + g];     bfr[1] = Bb[(4 + t) * 68 + g];
                mma_tf32(c, a, bfr);
            }
            int q = mi * 16 + g, d = ni * 8 + 2 * t;
            int qq = q0 + q;
            if (qq < NSc) {
                float inv = srow[q];
                int n = Jc + f * NSc + qq;
                *(float2*)(g_AO + ((size_t)b * Nc + n) * 512 + h * 64 + d) =
                    make_float2(c[0] * inv, c[1] * inv);
            }
            if (qq + 8 < NSc) {
                float inv = srow[q + 8];
                int n = Jc + f * NSc + qq + 8;
                *(float2*)(g_AO + ((size_t)b * Nc + n) * 512 + h * 64 + d) =
                    make_float2(c[2] * inv, c[3] * inv);
            }
        }
        __syncthreads();
    }
}

// -------- launch --------
extern "C" void kernel_launch(void* const* d_in, const int* in_sizes, int n_in,
                              void* d_out, int out_size) {
    const float* x     = (const float*)d_in[0];
    const float* w_qkv = (const float*)d_in[1];
    const float* w_out = (const float*)d_in[2];
    const float* b_out = (const float*)d_in[3];
    const float* sinp  = (const float*)d_in[4];
    const float* cosp  = (const float*)d_in[5];
    float* out = (float*)d_out;

    void *pqkv = nullptr, *pAO = nullptr;
    cudaGetSymbolAddress(&pqkv, g_qkv);
    cudaGetSymbolAddress(&pAO,  g_AO);

    const int JSMEM = (128*68*2 + 64*36 + 128*36 + 32*133 + 256 + 96) * 4;
    const int SSMEM = (224*68*2 + 64*36 + 224*36 + 32*233 + 256 + 32) * 4;
    cudaFuncSetAttribute(joints_attn_mma,
                         cudaFuncAttributeMaxDynamicSharedMemorySize, JSMEM);
    cudaFuncSetAttribute(spatial_attn_mma,
                         cudaFuncAttributeMaxDynamicSharedMemorySize, SSMEM);

    // 1) QKV GEMM
    dim3 g1(1536 / 128, MROWS / 64);
    tgemm64x128<<<g1, 256>>>(x, w_qkv, nullptr, (float*)pqkv, MROWS, 1536, 512);

    // 2) split + scale + RoPE
    int total = BHc * Nc * 64;
    split_rope_kernel<<<(total + 255) / 256, 256>>>(sinp, cosp);

    // 3) joints attention (flash MMA)
    joints_attn_mma<<<BHc, 256, JSMEM>>>();

    // 4) spatial attention (MMA)
    spatial_attn_mma<<<BHc * Fc, 256, SSMEM>>>();

    // 5) output GEMM
    dim3 g2(512 / 128, MROWS / 64);
    tgemm64x128<<<g2, 256>>>((const float*)pAO, w_out, b_out, out, MROWS, 512, 512);
}